// round 11
// baseline (speedup 1.0000x reference)
#include <cuda_runtime.h>

#define TIMES 4

// Probe (re-run of R9, previously lost to broker failure): write-through
// stores (__stwt) in place of __stcs — the single untested store-path
// variant. Everything else identical to the validated 76.9 µs configuration
// (256 thr, 1 float4/thread, 4 front-batched __ldcs loads, dependent
// FADD/FSETP/FSEL chain). Decision rule: keep iff kernel <= 76.5 µs.
__global__ __launch_bounds__(256) void spike_kernel(
    const float4* __restrict__ in, float4* __restrict__ out, int n_per_chunk /* float4 count */)
{
    int i = blockIdx.x * blockDim.x + threadIdx.x;
    if (i >= n_per_chunk) return;

    float4 I0 = __ldcs(&in[(size_t)0 * n_per_chunk + i]);
    float4 I1 = __ldcs(&in[(size_t)1 * n_per_chunk + i]);
    float4 I2 = __ldcs(&in[(size_t)2 * n_per_chunk + i]);
    float4 I3 = __ldcs(&in[(size_t)3 * n_per_chunk + i]);

    float4 V = make_float4(0.f, 0.f, 0.f, 0.f);

    #define STEP(I)                                                  \
        V.x += (I).x; V.y += (I).y; V.z += (I).z; V.w += (I).w;      \
        V.x = (fabsf(V.x) > 1.0f) ? 0.0f : V.x;                      \
        V.y = (fabsf(V.y) > 1.0f) ? 0.0f : V.y;                      \
        V.z = (fabsf(V.z) > 1.0f) ? 0.0f : V.z;                      \
        V.w = (fabsf(V.w) > 1.0f) ? 0.0f : V.w;

    STEP(I0); __stwt(&out[(size_t)0 * n_per_chunk + i], V);
    STEP(I1); __stwt(&out[(size_t)1 * n_per_chunk + i], V);
    STEP(I2); __stwt(&out[(size_t)2 * n_per_chunk + i], V);
    STEP(I3); __stwt(&out[(size_t)3 * n_per_chunk + i], V);

    #undef STEP
}

extern "C" void kernel_launch(void* const* d_in, const int* in_sizes, int n_in,
                              void* d_out, int out_size) {
    const float4* in = (const float4*)d_in[0];
    float4* out = (float4*)d_out;
    int n_per_chunk = out_size / TIMES / 4;  // float4 elements per chunk (4,194,304)
    int threads = 256;
    int blocks = (n_per_chunk + threads - 1) / threads;
    spike_kernel<<<blocks, threads>>>(in, out, n_per_chunk);
}

// round 12
// speedup vs baseline: 1.0151x; 1.0151x over previous
#include <cuda_runtime.h>

#define TIMES 4

// FINAL — at the hardware roofline: 6.25–6.31 TB/s (~79% of 8 TB/s spec),
// the sm_100a LTS/DRAM ceiling for a 1:1 single-touch read/write stream.
// Kernel time 76.9–77.5 µs reproduced across five benches.
//
// Exhaustively tested perturbations: 2x per-thread unroll (-1%), persistent
// one-wave grid (-9%), block 512 (neutral), __stwt write-through stores
// (-1%). Kept: __ldcs/__stcs streaming hints (+1%).
//
// SpikeActivation: V_t = reset(V_{t-1} + I_t), TIMES=4 chunks of [4096,4096].
// Time dimension carried in registers: 4 front-batched independent LDG.128s
// -> dependent FADD/FSETP/FSEL chain -> 4 STG.128s. Spatial dimension fully
// parallel and coalesced.
__global__ __launch_bounds__(256) void spike_kernel(
    const float4* __restrict__ in, float4* __restrict__ out, int n_per_chunk /* float4 count */)
{
    int i = blockIdx.x * blockDim.x + threadIdx.x;
    if (i >= n_per_chunk) return;

    float4 I0 = __ldcs(&in[(size_t)0 * n_per_chunk + i]);
    float4 I1 = __ldcs(&in[(size_t)1 * n_per_chunk + i]);
    float4 I2 = __ldcs(&in[(size_t)2 * n_per_chunk + i]);
    float4 I3 = __ldcs(&in[(size_t)3 * n_per_chunk + i]);

    float4 V = make_float4(0.f, 0.f, 0.f, 0.f);

    #define STEP(I)                                                  \
        V.x += (I).x; V.y += (I).y; V.z += (I).z; V.w += (I).w;      \
        V.x = (fabsf(V.x) > 1.0f) ? 0.0f : V.x;                      \
        V.y = (fabsf(V.y) > 1.0f) ? 0.0f : V.y;                      \
        V.z = (fabsf(V.z) > 1.0f) ? 0.0f : V.z;                      \
        V.w = (fabsf(V.w) > 1.0f) ? 0.0f : V.w;

    STEP(I0); __stcs(&out[(size_t)0 * n_per_chunk + i], V);
    STEP(I1); __stcs(&out[(size_t)1 * n_per_chunk + i], V);
    STEP(I2); __stcs(&out[(size_t)2 * n_per_chunk + i], V);
    STEP(I3); __stcs(&out[(size_t)3 * n_per_chunk + i], V);

    #undef STEP
}

extern "C" void kernel_launch(void* const* d_in, const int* in_sizes, int n_in,
                              void* d_out, int out_size) {
    const float4* in = (const float4*)d_in[0];
    float4* out = (float4*)d_out;
    int n_per_chunk = out_size / TIMES / 4;  // float4 elements per chunk (4,194,304)
    int threads = 256;
    int blocks = (n_per_chunk + threads - 1) / threads;
    spike_kernel<<<blocks, threads>>>(in, out, n_per_chunk);
}

// round 13
// speedup vs baseline: 1.0201x; 1.0049x over previous
#include <cuda_runtime.h>

#define TIMES 4

// FINAL — at the hardware roofline: 6.23–6.31 TB/s (~78–79% of 8 TB/s spec),
// the sm_100a LTS/DRAM ceiling for a 1:1 single-touch read/write stream.
// Kernel time 76.9–77.8 µs reproduced across six benches (e2e spread is
// harness noise on a bit-identical kernel).
//
// Exhaustively tested perturbations: 2x per-thread unroll (-1%), persistent
// one-wave grid (-9%), block 512 (neutral), __stwt write-through stores
// (-1%). Kept: __ldcs/__stcs streaming hints (+1%).
//
// SpikeActivation: V_t = reset(V_{t-1} + I_t), TIMES=4 chunks of [4096,4096].
// Time dimension carried in registers: 4 front-batched independent LDG.128s
// -> dependent FADD/FSETP/FSEL chain -> 4 STG.128s. Spatial dimension fully
// parallel and coalesced.
__global__ __launch_bounds__(256) void spike_kernel(
    const float4* __restrict__ in, float4* __restrict__ out, int n_per_chunk /* float4 count */)
{
    int i = blockIdx.x * blockDim.x + threadIdx.x;
    if (i >= n_per_chunk) return;

    float4 I0 = __ldcs(&in[(size_t)0 * n_per_chunk + i]);
    float4 I1 = __ldcs(&in[(size_t)1 * n_per_chunk + i]);
    float4 I2 = __ldcs(&in[(size_t)2 * n_per_chunk + i]);
    float4 I3 = __ldcs(&in[(size_t)3 * n_per_chunk + i]);

    float4 V = make_float4(0.f, 0.f, 0.f, 0.f);

    #define STEP(I)                                                  \
        V.x += (I).x; V.y += (I).y; V.z += (I).z; V.w += (I).w;      \
        V.x = (fabsf(V.x) > 1.0f) ? 0.0f : V.x;                      \
        V.y = (fabsf(V.y) > 1.0f) ? 0.0f : V.y;                      \
        V.z = (fabsf(V.z) > 1.0f) ? 0.0f : V.z;                      \
        V.w = (fabsf(V.w) > 1.0f) ? 0.0f : V.w;

    STEP(I0); __stcs(&out[(size_t)0 * n_per_chunk + i], V);
    STEP(I1); __stcs(&out[(size_t)1 * n_per_chunk + i], V);
    STEP(I2); __stcs(&out[(size_t)2 * n_per_chunk + i], V);
    STEP(I3); __stcs(&out[(size_t)3 * n_per_chunk + i], V);

    #undef STEP
}

extern "C" void kernel_launch(void* const* d_in, const int* in_sizes, int n_in,
                              void* d_out, int out_size) {
    const float4* in = (const float4*)d_in[0];
    float4* out = (float4*)d_out;
    int n_per_chunk = out_size / TIMES / 4;  // float4 elements per chunk (4,194,304)
    int threads = 256;
    int blocks = (n_per_chunk + threads - 1) / threads;
    spike_kernel<<<blocks, threads>>>(in, out, n_per_chunk);
}